// round 12
// baseline (speedup 1.0000x reference)
#include <cuda_runtime.h>
#include <math.h>

// Geometry: x (2,1,160,160,16), q/lambda (2,3,160,160,16), f32, C-order.
#define PP 2
#define XD 160
#define YD 160
#define LPB (XD*YD)
#define NV (PP*LPB*4)        // float4 count in x-shaped array = 204800
#define T_ITERS 48
#define TX 16
#define TY 8
#define NBX (XD/TX)          // 10
#define NBY (YD/TY)          // 20
#define NBLK (PP*NBX*NBY)    // 400
#define NTHR (TX*TY*4)       // 512
#define QS 32767.0f
#define FPAD 32              // one 128B line per flag

// Only boundary xbar crosses blocks -> double-buffered global (edges only used).
__device__ float4 g_xbg[2][NV];
__device__ unsigned int g_flags[NBLK*FPAD];

__global__ void kreset() {
    int i = blockIdx.x*blockDim.x + threadIdx.x;
    if (i < NBLK) g_flags[i*FPAD] = 0u;
}

__device__ __forceinline__ unsigned int ld_acq(const unsigned int* p) {
    unsigned int v;
    asm volatile("ld.acquire.gpu.global.u32 %0, [%1];" : "=r"(v) : "l"(p) : "memory");
    return v;
}
__device__ __forceinline__ void st_rel(unsigned int* p, unsigned int v) {
    asm volatile("st.release.gpu.global.u32 [%0], %1;" :: "l"(p), "r"(v) : "memory");
}

__device__ __forceinline__ float shfl_quad(float v, int lane, int delta4) {
    int src = (lane & ~3) | ((lane + delta4) & 3);
    return __shfl_sync(0xffffffffu, v, src);
}
__device__ __forceinline__ int shfl_quad_i(int v, int lane, int delta4) {
    int src = (lane & ~3) | ((lane + delta4) & 3);
    return __shfl_sync(0xffffffffu, v, src);
}
__device__ __forceinline__ float4 f4sub(float4 a, float4 b) {
    return make_float4(a.x-b.x, a.y-b.y, a.z-b.z, a.w-b.w);
}

struct I4 { int a, b, c, d; };
__device__ __forceinline__ I4 unpk(uint2 u) {
    I4 r;
    r.a = ((int)(u.x << 16)) >> 16;
    r.b = ((int)u.x) >> 16;
    r.c = ((int)(u.y << 16)) >> 16;
    r.d = ((int)u.y) >> 16;
    return r;
}
__device__ __forceinline__ uint2 lam2pk(float4 l) {
    int a = __float2int_rn(l.x * QS), b = __float2int_rn(l.y * QS);
    int c = __float2int_rn(l.z * QS), d = __float2int_rn(l.w * QS);
    uint2 u;
    u.x = ((unsigned)a & 0xffffu) | ((unsigned)b << 16);
    u.y = ((unsigned)c & 0xffffu) | ((unsigned)d << 16);
    return u;
}

// R8's proven qstep (cvt.rni.sat on the XU pipe — leave the busy alu pipe alone).
// Deterministic: identical inputs -> identical bits on owner and tracker paths.
__device__ __forceinline__ uint2 qstep_p(uint2 Q, uint2 L, float4 g, float ss) {
    short d0, d1, d2, d3;
    asm("cvt.rni.sat.s16.f32 %0, %1;" : "=h"(d0) : "f"(ss * g.x));
    asm("cvt.rni.sat.s16.f32 %0, %1;" : "=h"(d1) : "f"(ss * g.y));
    asm("cvt.rni.sat.s16.f32 %0, %1;" : "=h"(d2) : "f"(ss * g.z));
    asm("cvt.rni.sat.s16.f32 %0, %1;" : "=h"(d3) : "f"(ss * g.w));
    unsigned int lo, hi;
    asm("mov.b32 %0, {%1,%2};" : "=r"(lo) : "h"(d0), "h"(d1));
    asm("mov.b32 %0, {%1,%2};" : "=r"(hi) : "h"(d2), "h"(d3));
    uint2 r;
    r.x = __vmaxs2(__vmins2(__vaddss2(Q.x, lo), L.x), __vsubss2(0u, L.x));
    r.y = __vmaxs2(__vmins2(__vaddss2(Q.y, hi), L.y), __vsubss2(0u, L.y));
    return r;
}

__global__ void __launch_bounds__(NTHR, 3) kpersist(
    const float4* __restrict__ xn, const float4* __restrict__ lam,
    float4* __restrict__ out,
    float sigma, float sigma_s, float inv1ps, float tau, float tau_s, float theta)
{
    __shared__ float4 sxb[2][TX][TY][4];     // xbar tile, DOUBLE-BUFFERED
    __shared__ float4 sxn[NTHR];             // noisy input (constant)
    __shared__ uint2  slam[3*NTHR];          // own-site lambda (constant)
    __shared__ uint2  slamx[TY*4];           // lambda_0 at x-halo line (x0g-1, *)
    __shared__ uint2  slamy[TX*4];           // lambda_1 at y-halo line (*, y0g-1)

    int bid = blockIdx.x;
    int pp  = bid / (NBX*NBY);
    int t   = bid % (NBX*NBY);
    int bx  = t / NBY, by = t % NBY;
    int x0g = bx*TX, y0g = by*TY;

    int tid  = threadIdx.x;
    int quad = tid & 3;
    int ly   = (tid >> 2) & 7;
    int lx   = tid >> 5;           // warp index
    int lane = tid & 31;

    int base   = pp * LPB;
    int gx = x0g + lx, gy = y0g + ly;
    int line2d = gx*YD + gy;
    int gid    = (base + line2d)*4 + quad;

    // Cross-block xbar indices.
    int xti = (base + ((x0g+TX) % XD)*YD + gy)*4 + quad;          // +x edge
    int yti = (base + gx*YD + ((y0g+TY) % YD))*4 + quad;          // +y edge
    int hxl = (x0g == 0) ? XD-1 : x0g-1;
    int hyl = (y0g == 0) ? YD-1 : y0g-1;
    int lxg = (base + hxl*YD + gy)*4 + quad;                      // -x halo (lx==0)
    int lyg = (base + gx*YD + hyl)*4 + quad;                      // -y halo (ly==0)

    // Flag spin assigned to warp 1 (threads 32..35); warp 1 also owns the
    // end-of-iter bar.sync + flag store.
    int bxm = (bx == 0) ? NBX-1 : bx-1;
    int bxp = (bx == NBX-1) ? 0 : bx+1;
    int bym = (by == 0) ? NBY-1 : by-1;
    int byp = (by == NBY-1) ? 0 : by+1;
    const unsigned int* nflag = 0;
    if      (tid == 32) nflag = &g_flags[((pp*NBX + bxm)*NBY + by )*FPAD];
    else if (tid == 33) nflag = &g_flags[((pp*NBX + bxp)*NBY + by )*FPAD];
    else if (tid == 34) nflag = &g_flags[((pp*NBX + bx )*NBY + bym)*FPAD];
    else if (tid == 35) nflag = &g_flags[((pp*NBX + bx )*NBY + byp)*FPAD];
    unsigned int* myflag = &g_flags[bid*FPAD];

    bool pub = (lx == 0) | (lx == TX-1) | (ly == 0) | (ly == TY-1);

    // ---- prologue ----
    float4 v   = xn[gid];
    float4 pv  = v, x0v = v, xbv = v;
    sxn[tid] = v;
    #pragma unroll
    for (int d = 0; d < 3; d++)
        slam[d*NTHR + tid] = lam2pk(lam[((pp*3+d)*LPB + line2d)*4 + quad]);
    if (tid < TY*4) {                    // lambda_0 at (x0g-1, y0g+h)
        int h = tid >> 2, hq = tid & 3;
        slamx[tid] = lam2pk(lam[((pp*3+0)*LPB + hxl*YD + (y0g+h))*4 + hq]);
    } else if (tid < TY*4 + TX*4) {      // lambda_1 at (x0g+h, y0g-1)
        int t2 = tid - TY*4;
        int h = t2 >> 2, hq = t2 & 3;
        slamy[t2] = lam2pk(lam[((pp*3+1)*LPB + (x0g+h)*YD + hyl)*4 + hq]);
    }

    uint2 Q0  = make_uint2(0u,0u), Q1  = make_uint2(0u,0u), Q2 = make_uint2(0u,0u);
    uint2 Q0L = make_uint2(0u,0u), Q1L = make_uint2(0u,0u);   // tracked -x / -y site duals

    sxb[0][lx][ly][quad] = v;
    if (pub) g_xbg[0][gid] = v;

    __syncthreads();
    if (tid == 32) st_rel(myflag, 1u);   // xbar gen 0 published

    for (int k = 0; k < T_ITERS; k++) {
        const float4* gin = g_xbg[k & 1];
        unsigned int want = (unsigned int)(k + 1);

        // ===== single full barrier: 4 threads spin, rest sleep on BAR =====
        if (nflag) { while (ld_acq(nflag) < want) { } }
        __syncthreads();

        // ---- gen-k xbar neighbors: smem inside tile, L2 across block edges ----
        float4 xbx, xby, xbLx, xbLy;
        if (lx == TX-1) xbx  = __ldcv(gin + xti);            // warp 15 only
        else            xbx  = sxb[k&1][lx+1][ly][quad];
        if (lx == 0)    xbLx = __ldcv(gin + lxg);            // warp 0 only
        else            xbLx = sxb[k&1][lx-1][ly][quad];
        if (ly == TY-1) xby  = __ldcv(gin + yti);
        else            xby  = sxb[k&1][lx][ly+1][quad];
        if (ly == 0)    xbLy = __ldcv(gin + lyg);            // 4 lanes/warp

        // ---- t-direction + p (no cross-thread deps beyond quad shuffles) ----
        float nxt = shfl_quad(xbv.x, lane, 1);
        float4 gtv = make_float4(xbv.y-xbv.x, xbv.z-xbv.y, xbv.w-xbv.z, nxt-xbv.w);
        Q2 = qstep_p(Q2, slam[2*NTHR+tid], gtv, sigma_s);
        int q2d   = ((int)Q2.y) >> 16;
        int prevw = shfl_quad_i(q2d, lane, -1);

        float4 xnv = sxn[tid];
        pv.x = (pv.x + sigma*(xbv.x - xnv.x)) * inv1ps;
        pv.y = (pv.y + sigma*(xbv.y - xnv.y)) * inv1ps;
        pv.z = (pv.z + sigma*(xbv.z - xnv.z)) * inv1ps;
        pv.w = (pv.w + sigma*(xbv.w - xnv.w)) * inv1ps;

        // ---- own duals ----
        Q0 = qstep_p(Q0, slam[tid],      f4sub(xbx, xbv), sigma_s);
        Q1 = qstep_p(Q1, slam[NTHR+tid], f4sub(xby, xbv), sigma_s);

        // ---- tracked -x dual (bitwise = left owner's Q0) -> q0m, no barrier ----
        uint2 L0L = (lx > 0) ? slam[tid - 32] : slamx[lane & 31];
        Q0L = qstep_p(Q0L, L0L, f4sub(xbv, xbLx), sigma_s);

        // ---- q1m: warp shuffle (ly>0) or tracked -y dual (ly==0) ----
        uint2 Q1u;
        Q1u.x = __shfl_up_sync(0xffffffffu, Q1.x, 4);
        Q1u.y = __shfl_up_sync(0xffffffffu, Q1.y, 4);
        if (ly == 0) {
            uint2 L1L = slamy[(lx << 2) | quad];
            Q1L = qstep_p(Q1L, L1L, f4sub(xbv, xbLy), sigma_s);
            Q1u = Q1L;
        }

        // ---- divergence + primal update ----
        I4 q0  = unpk(Q0),  q1  = unpk(Q1),  q2 = unpk(Q2);
        I4 q0m = unpk(Q0L), q1m = unpk(Q1u);

        int adja = (q0m.a - q0.a) + (q1m.a - q1.a) + (prevw - q2.a);
        int adjb = (q0m.b - q0.b) + (q1m.b - q1.b) + (q2.a  - q2.b);
        int adjc = (q0m.c - q0.c) + (q1m.c - q1.c) + (q2.b  - q2.c);
        int adjd = (q0m.d - q0.d) + (q1m.d - q1.d) + (q2.c  - q2.d);

        float4 x1;
        x1.x = x0v.x - tau*pv.x - tau_s*__int2float_rn(adja);
        x1.y = x0v.y - tau*pv.y - tau_s*__int2float_rn(adjb);
        x1.z = x0v.z - tau*pv.z - tau_s*__int2float_rn(adjc);
        x1.w = x0v.w - tau*pv.w - tau_s*__int2float_rn(adjd);

        float opt = 1.0f + theta;
        float4 xbn;
        xbn.x = opt*x1.x - theta*x0v.x;
        xbn.y = opt*x1.y - theta*x0v.y;
        xbn.z = opt*x1.z - theta*x0v.z;
        xbn.w = opt*x1.w - theta*x0v.w;

        x0v = x1;
        xbv = xbn;

        if (k < T_ITERS-1) {
            sxb[(k+1)&1][lx][ly][quad] = xbv;     // other smem buffer: no WAR hazard
            if (pub) g_xbg[(k+1)&1][gid] = xbv;   // boundary publish
            // End-of-iter: producers arrive; warp 1 syncs, then stores flag.
            // Fast warps run into the next top __syncthreads, bounding skew to 1.
            if (lx == 1) {
                asm volatile("bar.sync 1, %0;" :: "r"(NTHR) : "memory");
                if (tid == 32) st_rel(myflag, (unsigned int)(k + 2));
            } else {
                asm volatile("bar.arrive 1, %0;" :: "r"(NTHR) : "memory");
            }
        }
    }

    out[gid] = x0v;                        // x1 after 48 iterations
}

extern "C" void kernel_launch(void* const* d_in, const int* in_sizes, int n_in,
                              void* d_out, int out_size) {
    const float4* x   = (const float4*)d_in[0];
    const float4* lam = (const float4*)d_in[1];
    float4* out = (float4*)d_out;

    cudaFuncSetAttribute(kpersist, cudaFuncAttributePreferredSharedMemoryCarveout, 100);

    float L     = sqrtf(13.0f);
    float s10   = 1.0f / (1.0f + expf(-10.0f));
    float sigma = s10 / L;
    float tau   = s10 / L;
    float theta = s10;
    float inv1ps  = 1.0f / (1.0f + sigma);
    float sigma_s = sigma * QS;
    float tau_s   = tau / QS;

    kreset<<<1, NBLK>>>();
    kpersist<<<NBLK, NTHR>>>(x, lam, out, sigma, sigma_s, inv1ps, tau, tau_s, theta);
}

// round 13
// speedup vs baseline: 1.4664x; 1.4664x over previous
#include <cuda_runtime.h>
#include <math.h>

// Geometry: x (2,1,160,160,16), q/lambda (2,3,160,160,16), f32, C-order.
#define PP 2
#define XD 160
#define YD 160
#define LPB (XD*YD)
#define NV (PP*LPB*4)        // float4 count in x-shaped array = 204800
#define T_ITERS 48
#define TX 16
#define TY 8
#define NBX (XD/TX)          // 10
#define NBY (YD/TY)          // 20
#define NBLK (PP*NBX*NBY)    // 400
#define NTHR (TX*TY*4)       // 512
#define QS 32767.0f
#define FPAD 32              // one 128B line per flag

// Only boundary xbar crosses blocks -> double-buffered global (edges only used).
__device__ float4 g_xbg[2][NV];
__device__ unsigned int g_flags[NBLK*FPAD];

__global__ void kreset() {
    int i = blockIdx.x*blockDim.x + threadIdx.x;
    if (i < NBLK) g_flags[i*FPAD] = 0u;
}

__device__ __forceinline__ unsigned int ld_acq(const unsigned int* p) {
    unsigned int v;
    asm volatile("ld.acquire.gpu.global.u32 %0, [%1];" : "=r"(v) : "l"(p) : "memory");
    return v;
}
__device__ __forceinline__ void st_rel(unsigned int* p, unsigned int v) {
    asm volatile("st.release.gpu.global.u32 [%0], %1;" :: "l"(p), "r"(v) : "memory");
}

__device__ __forceinline__ float shfl_quad(float v, int lane, int delta4) {
    int src = (lane & ~3) | ((lane + delta4) & 3);
    return __shfl_sync(0xffffffffu, v, src);
}
__device__ __forceinline__ int shfl_quad_i(int v, int lane, int delta4) {
    int src = (lane & ~3) | ((lane + delta4) & 3);
    return __shfl_sync(0xffffffffu, v, src);
}
__device__ __forceinline__ float4 f4sub(float4 a, float4 b) {
    return make_float4(a.x-b.x, a.y-b.y, a.z-b.z, a.w-b.w);
}

struct I4 { int a, b, c, d; };
__device__ __forceinline__ I4 unpk(uint2 u) {
    I4 r;
    r.a = ((int)(u.x << 16)) >> 16;
    r.b = ((int)u.x) >> 16;
    r.c = ((int)(u.y << 16)) >> 16;
    r.d = ((int)u.y) >> 16;
    return r;
}
__device__ __forceinline__ uint2 lam2pk(float4 l) {
    int a = __float2int_rn(l.x * QS), b = __float2int_rn(l.y * QS);
    int c = __float2int_rn(l.z * QS), d = __float2int_rn(l.w * QS);
    uint2 u;
    u.x = ((unsigned)a & 0xffffu) | ((unsigned)b << 16);
    u.y = ((unsigned)c & 0xffffu) | ((unsigned)d << 16);
    return u;
}

// R8's proven qstep (cvt.rni.sat on XU pipe). Deterministic across paths.
__device__ __forceinline__ uint2 qstep_p(uint2 Q, uint2 L, float4 g, float ss) {
    short d0, d1, d2, d3;
    asm("cvt.rni.sat.s16.f32 %0, %1;" : "=h"(d0) : "f"(ss * g.x));
    asm("cvt.rni.sat.s16.f32 %0, %1;" : "=h"(d1) : "f"(ss * g.y));
    asm("cvt.rni.sat.s16.f32 %0, %1;" : "=h"(d2) : "f"(ss * g.z));
    asm("cvt.rni.sat.s16.f32 %0, %1;" : "=h"(d3) : "f"(ss * g.w));
    unsigned int lo, hi;
    asm("mov.b32 %0, {%1,%2};" : "=r"(lo) : "h"(d0), "h"(d1));
    asm("mov.b32 %0, {%1,%2};" : "=r"(hi) : "h"(d2), "h"(d3));
    uint2 r;
    r.x = __vmaxs2(__vmins2(__vaddss2(Q.x, lo), L.x), __vsubss2(0u, L.x));
    r.y = __vmaxs2(__vmins2(__vaddss2(Q.y, hi), L.y), __vsubss2(0u, L.y));
    return r;
}

__global__ void __launch_bounds__(NTHR, 3) kpersist(
    const float4* __restrict__ xn, const float4* __restrict__ lam,
    float4* __restrict__ out,
    float sigma, float sigma_s, float inv1ps, float tau, float tau_s, float theta)
{
    __shared__ float4 sxb[TX][TY][4];        // xbar tile (current gen)
    __shared__ float4 sxn[NTHR];             // noisy input (constant)
    __shared__ uint2  slam[3*NTHR];          // lambda int16 packed (constant)
    __shared__ uint2  sq0[TX+1][TY][4];      // Q0' with left halo at [0]
    __shared__ uint2  sq1h[TX][4];           // Q1 halo col (y-dir uses shfl)

    int bid = blockIdx.x;
    int pp  = bid / (NBX*NBY);
    int t   = bid % (NBX*NBY);
    int bx  = t / NBY, by = t % NBY;
    int x0g = bx*TX, y0g = by*TY;

    int tid  = threadIdx.x;
    int quad = tid & 3;
    int ll   = tid >> 2;           // 0..127
    int lx   = ll >> 3;            // 0..15  (== warp index)
    int ly   = ll & 7;             // 0..7
    int lane = tid & 31;

    int base   = pp * LPB;
    int gx = x0g + lx, gy = y0g + ly;
    int line2d = gx*YD + gy;
    int gid    = (base + line2d)*4 + quad;

    // Out-of-tile +1 neighbor global indices (edge threads only).
    int xti = (base + ((x0g+TX) % XD)*YD + gy)*4 + quad;
    int yti = (base + gx*YD + ((y0g+TY) % YD))*4 + quad;

    // Lattice neighbors (flag sources). Centralized wait: threads 0..3 spin.
    int bxm = (bx == 0) ? NBX-1 : bx-1;
    int bxp = (bx == NBX-1) ? 0 : bx+1;
    int bym = (by == 0) ? NBY-1 : by-1;
    int byp = (by == NBY-1) ? 0 : by+1;
    const unsigned int* nflag = 0;
    if      (tid == 0) nflag = &g_flags[((pp*NBX + bxm)*NBY + by )*FPAD];
    else if (tid == 1) nflag = &g_flags[((pp*NBX + bxp)*NBY + by )*FPAD];
    else if (tid == 2) nflag = &g_flags[((pp*NBX + bx )*NBY + bym)*FPAD];
    else if (tid == 3) nflag = &g_flags[((pp*NBX + bx )*NBY + byp)*FPAD];
    unsigned int* myflag = &g_flags[bid*FPAD];

    bool pub = (lx == 0) | (lx == TX-1) | (ly == 0) | (ly == TY-1);
    bool xedge = (lx == TX-1);
    bool yedge = (ly == TY-1);

    // ---- prologue ----
    float4 v   = xn[gid];
    float4 pv  = v, x0v = v, xbv = v;
    sxn[tid] = v;
    #pragma unroll
    for (int d = 0; d < 3; d++)
        slam[d*NTHR + tid] = lam2pk(lam[((pp*3+d)*LPB + line2d)*4 + quad]);

    uint2 Q0 = make_uint2(0u,0u), Q1 = make_uint2(0u,0u), Q2 = make_uint2(0u,0u);

    sxb[lx][ly][quad] = v;
    if (pub) g_xbg[0][gid] = v;

    // ---- halo-tracker roles (threads 0..95) ----
    int    hgid = 0;
    uint2  hQ = make_uint2(0u,0u), hL = make_uint2(0u,0u);
    float4* hsrc = 0;
    uint2*  hdst = 0;
    if (tid < 32) {                      // Q0 halo line (x0g-1, y0g+h)
        int h   = tid >> 2;
        int hx  = (x0g == 0) ? XD-1 : x0g-1;
        int h2d = hx*YD + (y0g + h);
        hgid = (base + h2d)*4 + quad;
        hL   = lam2pk(lam[((pp*3+0)*LPB + h2d)*4 + quad]);
        hsrc = &sxb[0][h][quad];
        hdst = &sq0[0][h][quad];
    } else if (tid < 96) {               // Q1 halo line (x0g+h, y0g-1)
        int h   = (tid - 32) >> 2;
        int hy  = (y0g == 0) ? YD-1 : y0g-1;
        int h2d = (x0g + h)*YD + hy;
        hgid = (base + h2d)*4 + quad;
        hL   = lam2pk(lam[((pp*3+1)*LPB + h2d)*4 + quad]);
        hsrc = &sxb[h][0][quad];
        hdst = &sq1h[h][quad];
    }

    __syncthreads();
    if (tid == 480) st_rel(myflag, 1u);  // xbar gen 0 published (warp 15 owns flag)

    for (int k = 0; k < T_ITERS; k++) {
        const float4* gin = g_xbg[k & 1];
        unsigned int want = (unsigned int)(k + 1);

        // ===== Phase A: register/constant-smem-only work, hoisted above wait =====
        float nxt = shfl_quad(xbv.x, lane, 1);
        float4 gtv = make_float4(xbv.y-xbv.x, xbv.z-xbv.y, xbv.w-xbv.z, nxt-xbv.w);
        Q2 = qstep_p(Q2, slam[2*NTHR+tid], gtv, sigma_s);
        int q2d   = ((int)Q2.y) >> 16;
        int prevw = shfl_quad_i(q2d, lane, -1);

        float4 xnv = sxn[tid];
        pv.x = (pv.x + sigma*(xbv.x - xnv.x)) * inv1ps;
        pv.y = (pv.y + sigma*(xbv.y - xnv.y)) * inv1ps;
        pv.z = (pv.z + sigma*(xbv.z - xnv.z)) * inv1ps;
        pv.w = (pv.w + sigma*(xbv.w - xnv.w)) * inv1ps;

        // ===== Centralized wait: 4 threads spin, the rest sleep on BAR =====
        if (nflag) { while (ld_acq(nflag) < want) { } }
        __syncthreads();   // also orders sxb writes(k) -> reads(k) below

        // ===== Phase B: gen-k neighbor reads + duals =====
        float4 xbx = xedge ? __ldcv(gin + xti) : sxb[lx+1][ly][quad];
        float4 xby = yedge ? __ldcv(gin + yti) : sxb[lx][ly+1][quad];

        float4 gxv = f4sub(xbx, xbv);
        float4 gyv = f4sub(xby, xbv);

        Q0 = qstep_p(Q0, slam[tid],      gxv, sigma_s); sq0[lx+1][ly][quad] = Q0;
        Q1 = qstep_p(Q1, slam[NTHR+tid], gyv, sigma_s);

        uint2 Q1u;
        Q1u.x = __shfl_up_sync(0xffffffffu, Q1.x, 4);
        Q1u.y = __shfl_up_sync(0xffffffffu, Q1.y, 4);

        // halo Q tracked locally (bitwise = neighbor's owner value)
        if (tid < 96) {
            float4 a = __ldcv(gin + hgid);
            float4 b = *hsrc;
            hQ = qstep_p(hQ, hL, f4sub(b, a), sigma_s);
            *hdst = hQ;
        }

        __syncthreads();   // sq0/sq1h ready; also read(k) -> write(k+1) of sxb

        uint2 q0mp = sq0[lx][ly][quad];
        uint2 q1mp = (ly == 0) ? sq1h[lx][quad] : Q1u;

        I4 q0  = unpk(Q0),   q2 = unpk(Q2);
        I4 q1  = unpk(Q1);
        I4 q0m = unpk(q0mp), q1m = unpk(q1mp);

        int adja = (q0m.a - q0.a) + (q1m.a - q1.a) + (prevw - q2.a);
        int adjb = (q0m.b - q0.b) + (q1m.b - q1.b) + (q2.a  - q2.b);
        int adjc = (q0m.c - q0.c) + (q1m.c - q1.c) + (q2.b  - q2.c);
        int adjd = (q0m.d - q0.d) + (q1m.d - q1.d) + (q2.c  - q2.d);

        float4 x1;
        x1.x = x0v.x - tau*pv.x - tau_s*__int2float_rn(adja);
        x1.y = x0v.y - tau*pv.y - tau_s*__int2float_rn(adjb);
        x1.z = x0v.z - tau*pv.z - tau_s*__int2float_rn(adjc);
        x1.w = x0v.w - tau*pv.w - tau_s*__int2float_rn(adjd);

        float opt = 1.0f + theta;
        float4 xbn;
        xbn.x = opt*x1.x - theta*x0v.x;
        xbn.y = opt*x1.y - theta*x0v.y;
        xbn.z = opt*x1.z - theta*x0v.z;
        xbn.w = opt*x1.w - theta*x0v.w;

        x0v = x1;
        xbv = xbn;

        if (k < T_ITERS-1) {
            if (pub) g_xbg[(k+1) & 1][gid] = xbv;   // boundary publish
            sxb[lx][ly][quad] = xbv;                 // read(k)->write ordered by mid bar
            // End-of-iter: producers arrive on barrier 1; warp 15 syncs, then
            // publishes the flag. Fast warps run ahead into the next top
            // __syncthreads (which provides the sxb ordering), bounding skew.
            if (lx == 15) {
                asm volatile("bar.sync 1, %0;" :: "r"(NTHR) : "memory");
                if (tid == 480) st_rel(myflag, (unsigned int)(k + 2));
            } else {
                asm volatile("bar.arrive 1, %0;" :: "r"(NTHR) : "memory");
            }
        }
    }

    out[gid] = x0v;                        // x1 after 48 iterations
}

extern "C" void kernel_launch(void* const* d_in, const int* in_sizes, int n_in,
                              void* d_out, int out_size) {
    const float4* x   = (const float4*)d_in[0];
    const float4* lam = (const float4*)d_in[1];
    float4* out = (float4*)d_out;

    cudaFuncSetAttribute(kpersist, cudaFuncAttributePreferredSharedMemoryCarveout, 100);

    float L     = sqrtf(13.0f);
    float s10   = 1.0f / (1.0f + expf(-10.0f));
    float sigma = s10 / L;
    float tau   = s10 / L;
    float theta = s10;
    float inv1ps  = 1.0f / (1.0f + sigma);
    float sigma_s = sigma * QS;
    float tau_s   = tau / QS;

    kreset<<<1, NBLK>>>();
    kpersist<<<NBLK, NTHR>>>(x, lam, out, sigma, sigma_s, inv1ps, tau, tau_s, theta);
}

// round 14
// speedup vs baseline: 1.5097x; 1.0295x over previous
#include <cuda_runtime.h>
#include <math.h>

// Geometry: x (2,1,160,160,16), q/lambda (2,3,160,160,16), f32, C-order.
#define PP 2
#define XD 160
#define YD 160
#define LPB (XD*YD)
#define NV (PP*LPB*4)        // float4 count in x-shaped array = 204800
#define T_ITERS 48
#define TX 8
#define TY 8
#define NBX (XD/TX)          // 20
#define NBY (YD/TY)          // 20
#define NBLK (PP*NBX*NBY)    // 800
#define NTHR (TX*TY*4)       // 256
#define QS 32767.0f
#define FPAD 32              // one 128B line per flag

// Only boundary xbar crosses blocks -> double-buffered global (edges only used).
__device__ float4 g_xbg[2][NV];
__device__ unsigned int g_flags[NBLK*FPAD];

__global__ void kreset() {
    int i = blockIdx.x*blockDim.x + threadIdx.x;
    if (i < NBLK) g_flags[i*FPAD] = 0u;
}

__device__ __forceinline__ unsigned int ld_acq(const unsigned int* p) {
    unsigned int v;
    asm volatile("ld.acquire.gpu.global.u32 %0, [%1];" : "=r"(v) : "l"(p) : "memory");
    return v;
}
__device__ __forceinline__ void st_rel(unsigned int* p, unsigned int v) {
    asm volatile("st.release.gpu.global.u32 [%0], %1;" :: "l"(p), "r"(v) : "memory");
}

__device__ __forceinline__ float shfl_quad(float v, int lane, int delta4) {
    int src = (lane & ~3) | ((lane + delta4) & 3);
    return __shfl_sync(0xffffffffu, v, src);
}
__device__ __forceinline__ int shfl_quad_i(int v, int lane, int delta4) {
    int src = (lane & ~3) | ((lane + delta4) & 3);
    return __shfl_sync(0xffffffffu, v, src);
}
__device__ __forceinline__ float4 f4sub(float4 a, float4 b) {
    return make_float4(a.x-b.x, a.y-b.y, a.z-b.z, a.w-b.w);
}

struct I4 { int a, b, c, d; };
__device__ __forceinline__ I4 unpk(uint2 u) {
    I4 r;
    r.a = ((int)(u.x << 16)) >> 16;
    r.b = ((int)u.x) >> 16;
    r.c = ((int)(u.y << 16)) >> 16;
    r.d = ((int)u.y) >> 16;
    return r;
}
__device__ __forceinline__ uint2 lam2pk(float4 l) {
    int a = __float2int_rn(l.x * QS), b = __float2int_rn(l.y * QS);
    int c = __float2int_rn(l.z * QS), d = __float2int_rn(l.w * QS);
    uint2 u;
    u.x = ((unsigned)a & 0xffffu) | ((unsigned)b << 16);
    u.y = ((unsigned)c & 0xffffu) | ((unsigned)d << 16);
    return u;
}

// R8's proven qstep (cvt.rni.sat on XU pipe). Deterministic across paths.
__device__ __forceinline__ uint2 qstep_p(uint2 Q, uint2 L, float4 g, float ss) {
    short d0, d1, d2, d3;
    asm("cvt.rni.sat.s16.f32 %0, %1;" : "=h"(d0) : "f"(ss * g.x));
    asm("cvt.rni.sat.s16.f32 %0, %1;" : "=h"(d1) : "f"(ss * g.y));
    asm("cvt.rni.sat.s16.f32 %0, %1;" : "=h"(d2) : "f"(ss * g.z));
    asm("cvt.rni.sat.s16.f32 %0, %1;" : "=h"(d3) : "f"(ss * g.w));
    unsigned int lo, hi;
    asm("mov.b32 %0, {%1,%2};" : "=r"(lo) : "h"(d0), "h"(d1));
    asm("mov.b32 %0, {%1,%2};" : "=r"(hi) : "h"(d2), "h"(d3));
    uint2 r;
    r.x = __vmaxs2(__vmins2(__vaddss2(Q.x, lo), L.x), __vsubss2(0u, L.x));
    r.y = __vmaxs2(__vmins2(__vaddss2(Q.y, hi), L.y), __vsubss2(0u, L.y));
    return r;
}

__global__ void __launch_bounds__(NTHR, 6) kpersist(
    const float4* __restrict__ xn, const float4* __restrict__ lam,
    float4* __restrict__ out,
    float sigma, float sigma_s, float inv1ps, float tau, float tau_s, float theta)
{
    __shared__ float4 sxb[TX][TY][4];        // xbar tile (current gen)
    __shared__ float4 sxn[NTHR];             // noisy input (constant)
    __shared__ uint2  slam[3*NTHR];          // lambda int16 packed (constant)
    __shared__ uint2  sq0[TX+1][TY][4];      // Q0' with left halo at [0]
    __shared__ uint2  sq1h[TX][4];           // Q1 halo col (y-dir uses shfl)

    int bid = blockIdx.x;
    int pp  = bid / (NBX*NBY);
    int t   = bid % (NBX*NBY);
    int bx  = t / NBY, by = t % NBY;
    int x0g = bx*TX, y0g = by*TY;

    int tid  = threadIdx.x;
    int quad = tid & 3;
    int ll   = tid >> 2;           // 0..63
    int lx   = ll >> 3;            // 0..7  (== warp index)
    int ly   = ll & 7;             // 0..7
    int lane = tid & 31;

    int base   = pp * LPB;
    int gx = x0g + lx, gy = y0g + ly;
    int line2d = gx*YD + gy;
    int gid    = (base + line2d)*4 + quad;

    // Out-of-tile +1 neighbor global indices (edge threads only).
    int xti = (base + ((x0g+TX) % XD)*YD + gy)*4 + quad;
    int yti = (base + gx*YD + ((y0g+TY) % YD))*4 + quad;

    // Lattice neighbors (flag sources). Centralized wait: threads 0..3 spin.
    int bxm = (bx == 0) ? NBX-1 : bx-1;
    int bxp = (bx == NBX-1) ? 0 : bx+1;
    int bym = (by == 0) ? NBY-1 : by-1;
    int byp = (by == NBY-1) ? 0 : by+1;
    const unsigned int* nflag = 0;
    if      (tid == 0) nflag = &g_flags[((pp*NBX + bxm)*NBY + by )*FPAD];
    else if (tid == 1) nflag = &g_flags[((pp*NBX + bxp)*NBY + by )*FPAD];
    else if (tid == 2) nflag = &g_flags[((pp*NBX + bx )*NBY + bym)*FPAD];
    else if (tid == 3) nflag = &g_flags[((pp*NBX + bx )*NBY + byp)*FPAD];
    unsigned int* myflag = &g_flags[bid*FPAD];

    bool pub = (lx == 0) | (lx == TX-1) | (ly == 0) | (ly == TY-1);
    bool xedge = (lx == TX-1);
    bool yedge = (ly == TY-1);

    // ---- prologue ----
    float4 v   = xn[gid];
    float4 pv  = v, x0v = v, xbv = v;
    sxn[tid] = v;
    #pragma unroll
    for (int d = 0; d < 3; d++)
        slam[d*NTHR + tid] = lam2pk(lam[((pp*3+d)*LPB + line2d)*4 + quad]);

    uint2 Q0 = make_uint2(0u,0u), Q1 = make_uint2(0u,0u), Q2 = make_uint2(0u,0u);

    sxb[lx][ly][quad] = v;
    if (pub) g_xbg[0][gid] = v;

    // ---- halo-tracker roles (threads 0..63) ----
    int    hgid = 0;
    uint2  hQ = make_uint2(0u,0u), hL = make_uint2(0u,0u);
    float4* hsrc = 0;
    uint2*  hdst = 0;
    if (tid < 32) {                      // Q0 halo line (x0g-1, y0g+h)
        int h   = tid >> 2;
        int hx  = (x0g == 0) ? XD-1 : x0g-1;
        int h2d = hx*YD + (y0g + h);
        hgid = (base + h2d)*4 + quad;
        hL   = lam2pk(lam[((pp*3+0)*LPB + h2d)*4 + quad]);
        hsrc = &sxb[0][h][quad];
        hdst = &sq0[0][h][quad];
    } else if (tid < 64) {               // Q1 halo line (x0g+h, y0g-1)
        int h   = (tid - 32) >> 2;
        int hy  = (y0g == 0) ? YD-1 : y0g-1;
        int h2d = (x0g + h)*YD + hy;
        hgid = (base + h2d)*4 + quad;
        hL   = lam2pk(lam[((pp*3+1)*LPB + h2d)*4 + quad]);
        hsrc = &sxb[h][0][quad];
        hdst = &sq1h[h][quad];
    }

    __syncthreads();
    if (tid == 0) st_rel(myflag, 1u);    // xbar gen 0 published

    for (int k = 0; k < T_ITERS; k++) {
        const float4* gin = g_xbg[k & 1];
        unsigned int want = (unsigned int)(k + 1);

        // ===== Centralized wait: 4 threads spin, the rest sleep on BAR =====
        if (nflag) { while (ld_acq(nflag) < want) { } }
        __syncthreads();

        // ===== Phase B: gen-k neighbor reads + duals =====
        float4 xbx = xedge ? __ldcv(gin + xti) : sxb[lx+1][ly][quad];
        float4 xby = yedge ? __ldcv(gin + yti) : sxb[lx][ly+1][quad];

        float nxt = shfl_quad(xbv.x, lane, 1);
        float4 gtv = make_float4(xbv.y-xbv.x, xbv.z-xbv.y, xbv.w-xbv.z, nxt-xbv.w);
        float4 gxv = f4sub(xbx, xbv);
        float4 gyv = f4sub(xby, xbv);

        Q0 = qstep_p(Q0, slam[tid],        gxv, sigma_s); sq0[lx+1][ly][quad] = Q0;
        Q1 = qstep_p(Q1, slam[NTHR+tid],   gyv, sigma_s);
        Q2 = qstep_p(Q2, slam[2*NTHR+tid], gtv, sigma_s);

        uint2 Q1u;
        Q1u.x = __shfl_up_sync(0xffffffffu, Q1.x, 4);
        Q1u.y = __shfl_up_sync(0xffffffffu, Q1.y, 4);

        // halo Q tracked locally (bitwise = neighbor's owner value)
        if (tid < 64) {
            float4 a = __ldcv(gin + hgid);
            float4 b = *hsrc;
            hQ = qstep_p(hQ, hL, f4sub(b, a), sigma_s);
            *hdst = hQ;
        }

        // p update (registers only)
        float4 xnv = sxn[tid];
        pv.x = (pv.x + sigma*(xbv.x - xnv.x)) * inv1ps;
        pv.y = (pv.y + sigma*(xbv.y - xnv.y)) * inv1ps;
        pv.z = (pv.z + sigma*(xbv.z - xnv.z)) * inv1ps;
        pv.w = (pv.w + sigma*(xbv.w - xnv.w)) * inv1ps;

        __syncthreads();   // sq0/sq1h ready; also orders sxb read(k)->write(k+1)

        uint2 q0mp = sq0[lx][ly][quad];
        uint2 q1mp = (ly == 0) ? sq1h[lx][quad] : Q1u;

        I4 q0  = unpk(Q0),   q1  = unpk(Q1),   q2 = unpk(Q2);
        I4 q0m = unpk(q0mp), q1m = unpk(q1mp);
        int q2d   = q2.d;
        int prevw = shfl_quad_i(q2d, lane, -1);

        int adja = (q0m.a - q0.a) + (q1m.a - q1.a) + (prevw - q2.a);
        int adjb = (q0m.b - q0.b) + (q1m.b - q1.b) + (q2.a  - q2.b);
        int adjc = (q0m.c - q0.c) + (q1m.c - q1.c) + (q2.b  - q2.c);
        int adjd = (q0m.d - q0.d) + (q1m.d - q1.d) + (q2.c  - q2.d);

        float4 x1;
        x1.x = x0v.x - tau*pv.x - tau_s*__int2float_rn(adja);
        x1.y = x0v.y - tau*pv.y - tau_s*__int2float_rn(adjb);
        x1.z = x0v.z - tau*pv.z - tau_s*__int2float_rn(adjc);
        x1.w = x0v.w - tau*pv.w - tau_s*__int2float_rn(adjd);

        float opt = 1.0f + theta;
        float4 xbn;
        xbn.x = opt*x1.x - theta*x0v.x;
        xbn.y = opt*x1.y - theta*x0v.y;
        xbn.z = opt*x1.z - theta*x0v.z;
        xbn.w = opt*x1.w - theta*x0v.w;

        x0v = x1;
        xbv = xbn;

        if (k < T_ITERS-1) {
            if (pub) g_xbg[(k+1) & 1][gid] = xbv;   // boundary publish
            sxb[lx][ly][quad] = xbv;
            __syncthreads();
            if (tid == 0) st_rel(myflag, (unsigned int)(k + 2));
        }
    }

    out[gid] = x0v;                        // x1 after 48 iterations
}

extern "C" void kernel_launch(void* const* d_in, const int* in_sizes, int n_in,
                              void* d_out, int out_size) {
    const float4* x   = (const float4*)d_in[0];
    const float4* lam = (const float4*)d_in[1];
    float4* out = (float4*)d_out;

    cudaFuncSetAttribute(kpersist, cudaFuncAttributePreferredSharedMemoryCarveout, 100);

    float L     = sqrtf(13.0f);
    float s10   = 1.0f / (1.0f + expf(-10.0f));
    float sigma = s10 / L;
    float tau   = s10 / L;
    float theta = s10;
    float inv1ps  = 1.0f / (1.0f + sigma);
    float sigma_s = sigma * QS;
    float tau_s   = tau / QS;

    kreset<<<1, NBLK>>>();
    kpersist<<<NBLK, NTHR>>>(x, lam, out, sigma, sigma_s, inv1ps, tau, tau_s, theta);
}

// round 15
// speedup vs baseline: 1.5936x; 1.0556x over previous
#include <cuda_runtime.h>
#include <math.h>

// Geometry: x (2,1,160,160,16), q/lambda (2,3,160,160,16), f32, C-order.
#define PP 2
#define XD 160
#define YD 160
#define LPB (XD*YD)
#define NV (PP*LPB*4)        // float4 count in x-shaped array = 204800
#define T_ITERS 48
#define TX 8
#define TY 8
#define NBX (XD/TX)          // 20
#define NBY (YD/TY)          // 20
#define NBLK (PP*NBX*NBY)    // 800
#define NTHR (TX*TY*4)       // 256
#define QS 32767.0f
#define FPAD 32              // one 128B line per flag
#define SCATTER 83           // coprime to 400: co-resident blocks far apart

// Only boundary xbar crosses blocks -> double-buffered global (edges only used).
__device__ float4 g_xbg[2][NV];
__device__ unsigned int g_flags[NBLK*FPAD];

__global__ void kreset() {
    int i = blockIdx.x*blockDim.x + threadIdx.x;
    if (i < NBLK) g_flags[i*FPAD] = 0u;
}

__device__ __forceinline__ unsigned int ld_acq(const unsigned int* p) {
    unsigned int v;
    asm volatile("ld.acquire.gpu.global.u32 %0, [%1];" : "=r"(v) : "l"(p) : "memory");
    return v;
}
__device__ __forceinline__ void st_rel(unsigned int* p, unsigned int v) {
    asm volatile("st.release.gpu.global.u32 [%0], %1;" :: "l"(p), "r"(v) : "memory");
}

__device__ __forceinline__ float shfl_quad(float v, int lane, int delta4) {
    int src = (lane & ~3) | ((lane + delta4) & 3);
    return __shfl_sync(0xffffffffu, v, src);
}
__device__ __forceinline__ int shfl_quad_i(int v, int lane, int delta4) {
    int src = (lane & ~3) | ((lane + delta4) & 3);
    return __shfl_sync(0xffffffffu, v, src);
}
__device__ __forceinline__ float4 f4sub(float4 a, float4 b) {
    return make_float4(a.x-b.x, a.y-b.y, a.z-b.z, a.w-b.w);
}

struct I4 { int a, b, c, d; };
__device__ __forceinline__ I4 unpk(uint2 u) {
    I4 r;
    r.a = ((int)(u.x << 16)) >> 16;
    r.b = ((int)u.x) >> 16;
    r.c = ((int)(u.y << 16)) >> 16;
    r.d = ((int)u.y) >> 16;
    return r;
}
__device__ __forceinline__ uint2 lam2pk(float4 l) {
    int a = __float2int_rn(l.x * QS), b = __float2int_rn(l.y * QS);
    int c = __float2int_rn(l.z * QS), d = __float2int_rn(l.w * QS);
    uint2 u;
    u.x = ((unsigned)a & 0xffffu) | ((unsigned)b << 16);
    u.y = ((unsigned)c & 0xffffu) | ((unsigned)d << 16);
    return u;
}

// R8's proven qstep (cvt.rni.sat on XU pipe). Deterministic across paths.
__device__ __forceinline__ uint2 qstep_p(uint2 Q, uint2 L, float4 g, float ss) {
    short d0, d1, d2, d3;
    asm("cvt.rni.sat.s16.f32 %0, %1;" : "=h"(d0) : "f"(ss * g.x));
    asm("cvt.rni.sat.s16.f32 %0, %1;" : "=h"(d1) : "f"(ss * g.y));
    asm("cvt.rni.sat.s16.f32 %0, %1;" : "=h"(d2) : "f"(ss * g.z));
    asm("cvt.rni.sat.s16.f32 %0, %1;" : "=h"(d3) : "f"(ss * g.w));
    unsigned int lo, hi;
    asm("mov.b32 %0, {%1,%2};" : "=r"(lo) : "h"(d0), "h"(d1));
    asm("mov.b32 %0, {%1,%2};" : "=r"(hi) : "h"(d2), "h"(d3));
    uint2 r;
    r.x = __vmaxs2(__vmins2(__vaddss2(Q.x, lo), L.x), __vsubss2(0u, L.x));
    r.y = __vmaxs2(__vmins2(__vaddss2(Q.y, hi), L.y), __vsubss2(0u, L.y));
    return r;
}

__global__ void __launch_bounds__(NTHR, 6) kpersist(
    const float4* __restrict__ xn, const float4* __restrict__ lam,
    float4* __restrict__ out,
    float sigma, float sigma_s, float inv1ps, float tau, float tau_s, float theta)
{
    __shared__ float4 sxb[TX][TY][4];        // xbar tile (current gen)
    __shared__ float4 sxn[NTHR];             // noisy input (constant)
    __shared__ uint2  slam[3*NTHR];          // lambda int16 packed (constant)
    __shared__ uint2  sq0[TX+1][TY][4];      // Q0' with left halo at [0]
    __shared__ uint2  sq1h[TX][4];           // Q1 halo col (y-dir uses shfl)

    int bid = blockIdx.x;
    int pp  = bid / (NBX*NBY);
    // SCATTER: consecutive bids (co-resident on an SM) map to far-apart tiles,
    // decorrelating their sync phases. Pure relabeling; flags indexed by tile.
    int t   = (int)(((long long)(bid % (NBX*NBY)) * SCATTER) % (NBX*NBY));
    int bx  = t / NBY, by = t % NBY;
    int x0g = bx*TX, y0g = by*TY;
    int tile = pp*(NBX*NBY) + t;

    int tid  = threadIdx.x;
    int quad = tid & 3;
    int ll   = tid >> 2;           // 0..63
    int lx   = ll >> 3;            // 0..7  (== warp index)
    int ly   = ll & 7;             // 0..7
    int lane = tid & 31;

    int base   = pp * LPB;
    int gx = x0g + lx, gy = y0g + ly;
    int line2d = gx*YD + gy;
    int gid    = (base + line2d)*4 + quad;

    // Out-of-tile +1 neighbor global indices (edge threads only).
    int xti = (base + ((x0g+TX) % XD)*YD + gy)*4 + quad;
    int yti = (base + gx*YD + ((y0g+TY) % YD))*4 + quad;

    // Lattice neighbors (flag sources, indexed by TILE). Threads 0..3 spin.
    int bxm = (bx == 0) ? NBX-1 : bx-1;
    int bxp = (bx == NBX-1) ? 0 : bx+1;
    int bym = (by == 0) ? NBY-1 : by-1;
    int byp = (by == NBY-1) ? 0 : by+1;
    const unsigned int* nflag = 0;
    if      (tid == 0) nflag = &g_flags[((pp*NBX + bxm)*NBY + by )*FPAD];
    else if (tid == 1) nflag = &g_flags[((pp*NBX + bxp)*NBY + by )*FPAD];
    else if (tid == 2) nflag = &g_flags[((pp*NBX + bx )*NBY + bym)*FPAD];
    else if (tid == 3) nflag = &g_flags[((pp*NBX + bx )*NBY + byp)*FPAD];
    unsigned int* myflag = &g_flags[tile*FPAD];

    bool pub = (lx == 0) | (lx == TX-1) | (ly == 0) | (ly == TY-1);
    bool xedge = (lx == TX-1);
    bool yedge = (ly == TY-1);

    // ---- prologue ----
    float4 v   = xn[gid];
    float4 pv  = v, x0v = v, xbv = v;
    sxn[tid] = v;
    #pragma unroll
    for (int d = 0; d < 3; d++)
        slam[d*NTHR + tid] = lam2pk(lam[((pp*3+d)*LPB + line2d)*4 + quad]);

    uint2 Q0 = make_uint2(0u,0u), Q1 = make_uint2(0u,0u), Q2 = make_uint2(0u,0u);

    sxb[lx][ly][quad] = v;
    if (pub) g_xbg[0][gid] = v;

    // ---- halo-tracker roles (threads 0..63) ----
    int    hgid = 0;
    uint2  hQ = make_uint2(0u,0u), hL = make_uint2(0u,0u);
    float4* hsrc = 0;
    uint2*  hdst = 0;
    if (tid < 32) {                      // Q0 halo line (x0g-1, y0g+h)
        int h   = tid >> 2;
        int hx  = (x0g == 0) ? XD-1 : x0g-1;
        int h2d = hx*YD + (y0g + h);
        hgid = (base + h2d)*4 + quad;
        hL   = lam2pk(lam[((pp*3+0)*LPB + h2d)*4 + quad]);
        hsrc = &sxb[0][h][quad];
        hdst = &sq0[0][h][quad];
    } else if (tid < 64) {               // Q1 halo line (x0g+h, y0g-1)
        int h   = (tid - 32) >> 2;
        int hy  = (y0g == 0) ? YD-1 : y0g-1;
        int h2d = (x0g + h)*YD + hy;
        hgid = (base + h2d)*4 + quad;
        hL   = lam2pk(lam[((pp*3+1)*LPB + h2d)*4 + quad]);
        hsrc = &sxb[h][0][quad];
        hdst = &sq1h[h][quad];
    }

    __syncthreads();
    if (tid == 0) st_rel(myflag, 1u);    // xbar gen 0 published

    for (int k = 0; k < T_ITERS; k++) {
        const float4* gin = g_xbg[k & 1];
        unsigned int want = (unsigned int)(k + 1);

        // ===== Centralized wait: 4 threads spin, the rest sleep on BAR =====
        if (nflag) { while (ld_acq(nflag) < want) { } }
        __syncthreads();

        // ===== Phase B: gen-k neighbor reads + duals =====
        float4 xbx = xedge ? __ldcv(gin + xti) : sxb[lx+1][ly][quad];
        float4 xby = yedge ? __ldcv(gin + yti) : sxb[lx][ly+1][quad];

        float nxt = shfl_quad(xbv.x, lane, 1);
        float4 gtv = make_float4(xbv.y-xbv.x, xbv.z-xbv.y, xbv.w-xbv.z, nxt-xbv.w);
        float4 gxv = f4sub(xbx, xbv);
        float4 gyv = f4sub(xby, xbv);

        Q0 = qstep_p(Q0, slam[tid],        gxv, sigma_s); sq0[lx+1][ly][quad] = Q0;
        Q1 = qstep_p(Q1, slam[NTHR+tid],   gyv, sigma_s);
        Q2 = qstep_p(Q2, slam[2*NTHR+tid], gtv, sigma_s);

        uint2 Q1u;
        Q1u.x = __shfl_up_sync(0xffffffffu, Q1.x, 4);
        Q1u.y = __shfl_up_sync(0xffffffffu, Q1.y, 4);

        // halo Q tracked locally (bitwise = neighbor's owner value)
        if (tid < 64) {
            float4 a = __ldcv(gin + hgid);
            float4 b = *hsrc;
            hQ = qstep_p(hQ, hL, f4sub(b, a), sigma_s);
            *hdst = hQ;
        }

        // p update (registers only)
        float4 xnv = sxn[tid];
        pv.x = (pv.x + sigma*(xbv.x - xnv.x)) * inv1ps;
        pv.y = (pv.y + sigma*(xbv.y - xnv.y)) * inv1ps;
        pv.z = (pv.z + sigma*(xbv.z - xnv.z)) * inv1ps;
        pv.w = (pv.w + sigma*(xbv.w - xnv.w)) * inv1ps;

        __syncthreads();   // sq0/sq1h ready; also orders sxb read(k)->write(k+1)

        uint2 q0mp = sq0[lx][ly][quad];
        uint2 q1mp = (ly == 0) ? sq1h[lx][quad] : Q1u;

        I4 q0  = unpk(Q0),   q1  = unpk(Q1),   q2 = unpk(Q2);
        I4 q0m = unpk(q0mp), q1m = unpk(q1mp);
        int prevw = shfl_quad_i(q2.d, lane, -1);

        int adja = (q0m.a - q0.a) + (q1m.a - q1.a) + (prevw - q2.a);
        int adjb = (q0m.b - q0.b) + (q1m.b - q1.b) + (q2.a  - q2.b);
        int adjc = (q0m.c - q0.c) + (q1m.c - q1.c) + (q2.b  - q2.c);
        int adjd = (q0m.d - q0.d) + (q1m.d - q1.d) + (q2.c  - q2.d);

        float4 x1;
        x1.x = x0v.x - tau*pv.x - tau_s*__int2float_rn(adja);
        x1.y = x0v.y - tau*pv.y - tau_s*__int2float_rn(adjb);
        x1.z = x0v.z - tau*pv.z - tau_s*__int2float_rn(adjc);
        x1.w = x0v.w - tau*pv.w - tau_s*__int2float_rn(adjd);

        float opt = 1.0f + theta;
        float4 xbn;
        xbn.x = opt*x1.x - theta*x0v.x;
        xbn.y = opt*x1.y - theta*x0v.y;
        xbn.z = opt*x1.z - theta*x0v.z;
        xbn.w = opt*x1.w - theta*x0v.w;

        x0v = x1;
        xbv = xbn;

        if (k < T_ITERS-1) {
            if (pub) g_xbg[(k+1) & 1][gid] = xbv;   // boundary publish
            sxb[lx][ly][quad] = xbv;
            __syncthreads();
            if (tid == 0) st_rel(myflag, (unsigned int)(k + 2));
        }
    }

    out[gid] = x0v;                        // x1 after 48 iterations
}

extern "C" void kernel_launch(void* const* d_in, const int* in_sizes, int n_in,
                              void* d_out, int out_size) {
    const float4* x   = (const float4*)d_in[0];
    const float4* lam = (const float4*)d_in[1];
    float4* out = (float4*)d_out;

    cudaFuncSetAttribute(kpersist, cudaFuncAttributePreferredSharedMemoryCarveout, 100);

    float L     = sqrtf(13.0f);
    float s10   = 1.0f / (1.0f + expf(-10.0f));
    float sigma = s10 / L;
    float tau   = s10 / L;
    float theta = s10;
    float inv1ps  = 1.0f / (1.0f + sigma);
    float sigma_s = sigma * QS;
    float tau_s   = tau / QS;

    kreset<<<1, NBLK>>>();
    kpersist<<<NBLK, NTHR>>>(x, lam, out, sigma, sigma_s, inv1ps, tau, tau_s, theta);
}